// round 7
// baseline (speedup 1.0000x reference)
#include <cuda_runtime.h>
#include <cuda_fp16.h>

#define NA 16       // agents
#define ND 256      // action dim (K of the GEMM)
#define NN 64       // K_kernels * NA = output cols (N of the GEMM)
#define MT 192      // rows per CTA (12 warps x 16)
#define NTHREADS 384
#define NWARPS 12
#define NSTAGES 6   // per-warp cp.async A stages (1KB each)
#define PIPE_D 4    // wait_group depth

// dynamic smem layout (bytes)
#define SB_OFF    0                        // B tile fp16: 32KB
#define SA_OFF    32768                    // A ring: 12 warps * 6 stages * 1KB = 72KB
#define SKERN_OFF (32768 + NWARPS*NSTAGES*1024)
#define SBIAS_OFF (SKERN_OFF + 256)
#define SMEM_TOTAL (SBIAS_OFF + 256)

__device__ __forceinline__ unsigned pack_h2(float a, float b) {
    __half2 h = __floats2half2_rn(a, b);
    return *reinterpret_cast<unsigned*>(&h);
}

#define CP_ASYNC_CG16(dst_u32, src_ptr) \
    asm volatile("cp.async.cg.shared.global [%0], [%1], 16;\n" :: "r"(dst_u32), "l"(src_ptr))
#define CP_COMMIT()  asm volatile("cp.async.commit_group;\n" ::: "memory")
#define CP_WAIT()    asm volatile("cp.async.wait_group %0;\n" :: "n"(PIPE_D) : "memory")

// ---------------------------------------------------------------------------
// Single fused kernel: B converted from si_W inline (K-permuted, swizzled),
// GEMM (M=Btot, K=256, N=64) fp16 mma.sync, per-warp cp.async A ring,
// fused sigmoid/kern/adv epilogue. CTA 0 writes the 5 scalar tail outputs.
// ---------------------------------------------------------------------------
__global__ void __launch_bounds__(NTHREADS, 2)
mixer_kernel(const float* __restrict__ aq,
             const float* __restrict__ acts,
             const float* __restrict__ mq,
             const float* __restrict__ Vp,
             const float* __restrict__ sel,
             const float* __restrict__ keysp,
             const float* __restrict__ si_keys,
             const float* __restrict__ si_agents,
             const float* __restrict__ si_W,
             const float* __restrict__ si_b,
             float* __restrict__ out,
             int Btot, int out_size)
{
    extern __shared__ char smem[];
    __half* sB    = reinterpret_cast<__half*>(smem + SB_OFF);
    float4* sA4   = reinterpret_cast<float4*>(smem + SA_OFF);
    float*  sKern = reinterpret_cast<float*>(smem + SKERN_OFF);
    float*  sBias = reinterpret_cast<float*>(smem + SBIAS_OFF);

    const int tid = threadIdx.x;

    // kern[n] = (|si_keys[k]|+1e-10) * sigmoid(si_agents[k][a]); bias[n] = si_b
    if (tid < NN) {
        int k = tid >> 4;
        float sg = 1.0f / (1.0f + __expf(-si_agents[tid]));
        sKern[tid] = (fabsf(si_keys[k]) + 1e-10f) * sg;
        sBias[tid] = si_b[tid];
    }

    // scalar tail outputs (one thread of one CTA)
    if (blockIdx.x == 0 && tid == NTHREADS - 1 && out_size >= Btot + 5) {
        float ssq = 0.f;
        for (int h = 0; h < 4; ++h) {
            float d = 0.f;
            for (int e = 0; e < 64; ++e) d = fmaf(sel[h * 64 + e], keysp[h * 64 + e], d);
            ssq += d * d;
        }
        out[Btot] = 0.001f * ssq;                  // attend_mag_regs
        float aw = 0.0625f;                         // softmax of equal logits
        float ent = -16.0f * (logf(aw + 1e-8f) * aw);
        for (int h = 0; h < 4; ++h) out[Btot + 1 + h] = ent;  // head_entropies
    }

    // Stage B from si_W (fp32, L2-hot): K-permutation fused into packing.
    // For each (row r, 16-col block blk): dest seg(2blk)   = xy of 4 float4s,
    //                                     dest seg(2blk+1) = zw of 4 float4s.
    // Swizzle: seg' = seg ^ (r & 7); 16B segments.
    for (int s = tid; s < 64 * 16; s += NTHREADS) {
        int r = s >> 4, blk = s & 15;
        const float4* src = reinterpret_cast<const float4*>(si_W + r * ND + blk * 16);
        float4 f0 = src[0], f1 = src[1], f2 = src[2], f3 = src[3];
        uint4 seg0, seg1;
        seg0.x = pack_h2(f0.x, f0.y); seg0.y = pack_h2(f1.x, f1.y);
        seg0.z = pack_h2(f2.x, f2.y); seg0.w = pack_h2(f3.x, f3.y);
        seg1.x = pack_h2(f0.z, f0.w); seg1.y = pack_h2(f1.z, f1.w);
        seg1.z = pack_h2(f2.z, f2.w); seg1.w = pack_h2(f3.z, f3.w);
        int c0 = 2 * blk, c1 = 2 * blk + 1;
        *reinterpret_cast<uint4*>(sB + r * ND + ((c0 ^ (r & 7)) << 3)) = seg0;
        *reinterpret_cast<uint4*>(sB + r * ND + ((c1 ^ (r & 7)) << 3)) = seg1;
    }
    __syncthreads();

    const int w = tid >> 5, l = tid & 31;
    const int quad = l >> 2, qid = l & 3;
    const int l7 = l & 7, t8 = l >> 3;
    const long warpRow0 = (long)blockIdx.x * MT + w * 16;

    long r0 = warpRow0 + quad;
    long r1 = r0 + 8;
    long r0c = (r0 < Btot) ? r0 : (long)(Btot - 1);
    long r1c = (r1 < Btot) ? r1 : (long)(Btot - 1);
    const int cA = qid * 2;

    // cp.async lane geometry: 2 segments/lane/stage
    const int ldRowA = l >> 2;
    const int ldC4A  = l & 3;
    long gRow0 = warpRow0 + ldRowA;       if (gRow0 >= Btot) gRow0 = Btot - 1;
    long gRow1 = warpRow0 + 8 + ldRowA;   if (gRow1 >= Btot) gRow1 = Btot - 1;
    const float* gA0 = acts + gRow0 * ND + ldC4A * 4;
    const float* gA1 = acts + gRow1 * ND + ldC4A * 4;

    const unsigned sAaddr = (unsigned)__cvta_generic_to_shared(sA4);
    const unsigned sBaddr = (unsigned)__cvta_generic_to_shared(sB);
    const unsigned segOff0 = (unsigned)((ldRowA * 4 + ldC4A) * 16);
    const unsigned segOff1 = segOff0 + 8 * 4 * 16;

    // B ldmatrix lane geometry
    const int rowB_off = (t8 >> 1) * 8 + l7;
    const int s0B = t8 & 1;

    float acc[8][4];
#pragma unroll
    for (int i = 0; i < 8; ++i)
#pragma unroll
        for (int j = 0; j < 4; ++j) acc[i][j] = 0.f;

    // prologue: stages for kk = 0..PIPE_D-1
#pragma unroll
    for (int kk = 0; kk < PIPE_D; ++kk) {
        unsigned stBase = sAaddr + (unsigned)((w * NSTAGES + kk) * 1024);
        CP_ASYNC_CG16(stBase + segOff0, gA0 + kk * 16);
        CP_ASYNC_CG16(stBase + segOff1, gA1 + kk * 16);
        CP_COMMIT();
    }

#pragma unroll
    for (int kk = 0; kk < 16; ++kk) {
        // issue stage kk+PIPE_D
        if (kk + PIPE_D < 16) {
            unsigned stBase = sAaddr + (unsigned)((w * NSTAGES + ((kk + PIPE_D) % NSTAGES)) * 1024);
            CP_ASYNC_CG16(stBase + segOff0, gA0 + (kk + PIPE_D) * 16);
            CP_ASYNC_CG16(stBase + segOff1, gA1 + (kk + PIPE_D) * 16);
        }
        CP_COMMIT();
        CP_WAIT();            // stage kk complete (outstanding <= PIPE_D)
        __syncwarp();

        const float4* st = sA4 + (w * NSTAGES + (kk % NSTAGES)) * 64;
        float4 f0 = st[quad * 4 + qid];
        float4 f1 = st[(quad + 8) * 4 + qid];
        unsigned a0 = pack_h2(f0.x, f0.y);
        unsigned a1 = pack_h2(f1.x, f1.y);
        unsigned a2 = pack_h2(f0.z, f0.w);
        unsigned a3 = pack_h2(f1.z, f1.w);
#pragma unroll
        for (int p = 0; p < 4; ++p) {
            unsigned addrB = sBaddr
                           + (unsigned)((p * 16 + rowB_off) * (ND * 2))
                           + (unsigned)(((kk * 2 + s0B) ^ l7) << 4);
            unsigned b0, b1, b2, b3;
            asm volatile("ldmatrix.sync.aligned.m8n8.x4.shared.b16 {%0,%1,%2,%3}, [%4];\n"
                         : "=r"(b0), "=r"(b1), "=r"(b2), "=r"(b3) : "r"(addrB));
            asm volatile("mma.sync.aligned.m16n8k16.row.col.f32.f16.f16.f32 "
                         "{%0,%1,%2,%3}, {%4,%5,%6,%7}, {%8,%9}, {%0,%1,%2,%3};\n"
                         : "+f"(acc[2*p][0]), "+f"(acc[2*p][1]),
                           "+f"(acc[2*p][2]), "+f"(acc[2*p][3])
                         : "r"(a0), "r"(a1), "r"(a2), "r"(a3), "r"(b0), "r"(b1));
            asm volatile("mma.sync.aligned.m16n8k16.row.col.f32.f16.f16.f32 "
                         "{%0,%1,%2,%3}, {%4,%5,%6,%7}, {%8,%9}, {%0,%1,%2,%3};\n"
                         : "+f"(acc[2*p+1][0]), "+f"(acc[2*p+1][1]),
                           "+f"(acc[2*p+1][2]), "+f"(acc[2*p+1][3])
                         : "r"(a0), "r"(a1), "r"(a2), "r"(a3), "r"(b2), "r"(b3));
        }
        __syncwarp();
    }

    // Epilogue. acc[nt][h*2+j] = logit for row (r0 + h*8), col n = nt*8 + cA + j.
    const float v = Vp[0] * 0.0625f;
    float partial[2] = {0.f, 0.f};
#pragma unroll
    for (int h = 0; h < 2; ++h) {
        long gr = (h == 0) ? r0c : r1c;
        const float* aqr = aq + gr * NA;
        const float* mqr = mq + gr * NA;
#pragma unroll
        for (int j = 0; j < 2; ++j) {
#pragma unroll
            for (int pp = 0; pp < 2; ++pp) {
                float s = 0.f;
#pragma unroll
                for (int q = 0; q < 4; ++q) {
                    int nt = 2 * q + pp;
                    int n = nt * 8 + cA + j;
                    float x = acc[nt][h * 2 + j] + sBias[n];
                    x = 1.0f / (1.0f + __expf(-x));
                    s = fmaf(x, sKern[n], s);
                }
                int a = cA + j + 8 * pp;
                float advq = fmaf(0.25f, __ldcs(aqr + a), v)
                           - fmaf(0.25f, __ldcs(mqr + a), v);
                partial[h] += advq * (s - 1.0f);
            }
        }
    }
    partial[0] += __shfl_xor_sync(0xffffffffu, partial[0], 1);
    partial[0] += __shfl_xor_sync(0xffffffffu, partial[0], 2);
    partial[1] += __shfl_xor_sync(0xffffffffu, partial[1], 1);
    partial[1] += __shfl_xor_sync(0xffffffffu, partial[1], 2);
    if (qid == 0) {
        if (r0 < Btot) out[r0] = partial[0];
        if (r1 < Btot) out[r1] = partial[1];
    }
}

// ---------------------------------------------------------------------------
extern "C" void kernel_launch(void* const* d_in, const int* in_sizes, int n_in,
                              void* d_out, int out_size)
{
    const float* agent_qs  = (const float*)d_in[0];
    const float* actions   = (const float*)d_in[1];
    const float* max_q_i   = (const float*)d_in[2];
    const float* selectors = (const float*)d_in[3];
    const float* keys      = (const float*)d_in[4];
    const float* V         = (const float*)d_in[5];
    const float* si_keys   = (const float*)d_in[6];
    const float* si_agents = (const float*)d_in[7];
    const float* si_W      = (const float*)d_in[8];
    const float* si_b      = (const float*)d_in[9];
    float* out = (float*)d_out;

    int Btot = in_sizes[0] / NA;   // B0*T

    cudaFuncSetAttribute(mixer_kernel,
                         cudaFuncAttributeMaxDynamicSharedMemorySize, SMEM_TOTAL);

    int grid = (Btot + MT - 1) / MT;
    mixer_kernel<<<grid, NTHREADS, SMEM_TOTAL>>>(agent_qs, actions, max_q_i, V,
                                                 selectors, keys,
                                                 si_keys, si_agents, si_W, si_b,
                                                 out, Btot, out_size);
}

// round 8
// speedup vs baseline: 1.0332x; 1.0332x over previous
#include <cuda_runtime.h>
#include <cuda_fp16.h>

#define NA 16       // agents
#define ND 256      // action dim (K of the GEMM)
#define NN 64       // K_kernels * NA = output cols (N of the GEMM)
#define MT 128      // rows per CTA (8 warps x 16)
#define NTHREADS 256
#define NWARPS 8
#define NSTAGES 5   // per-warp cp.async A stages (1KB each)
#define PIPE_D 3    // wait_group depth

// dynamic smem layout (bytes)
#define SB_OFF    0                        // B tile fp16: 32KB
#define SA_OFF    32768                    // A ring: 8 warps * 5 stages * 1KB = 40KB
#define SKERN_OFF (32768 + NWARPS*NSTAGES*1024)
#define SBIAS_OFF (SKERN_OFF + 256)
#define SMEM_TOTAL (SBIAS_OFF + 256)       // 74240 -> 3 CTAs/SM

__device__ __forceinline__ unsigned pack_h2(float a, float b) {
    __half2 h = __floats2half2_rn(a, b);
    return *reinterpret_cast<unsigned*>(&h);
}

#define CP_ASYNC_CG16(dst_u32, src_ptr) \
    asm volatile("cp.async.cg.shared.global [%0], [%1], 16;\n" :: "r"(dst_u32), "l"(src_ptr))
#define CP_COMMIT()  asm volatile("cp.async.commit_group;\n" ::: "memory")
#define CP_WAIT()    asm volatile("cp.async.wait_group %0;\n" :: "n"(PIPE_D) : "memory")

// ---------------------------------------------------------------------------
// Single fused kernel: B converted from si_W inline (K-permuted, swizzled),
// GEMM (M=Btot, K=256, N=64) fp16 mma.sync, per-warp lane-private cp.async
// A ring (no intra-loop syncs), hoisted adv_q loads, fused epilogue.
// ---------------------------------------------------------------------------
__global__ void __launch_bounds__(NTHREADS, 3)
mixer_kernel(const float* __restrict__ aq,
             const float* __restrict__ acts,
             const float* __restrict__ mq,
             const float* __restrict__ Vp,
             const float* __restrict__ sel,
             const float* __restrict__ keysp,
             const float* __restrict__ si_keys,
             const float* __restrict__ si_agents,
             const float* __restrict__ si_W,
             const float* __restrict__ si_b,
             float* __restrict__ out,
             int Btot, int out_size)
{
    extern __shared__ char smem[];
    __half* sB    = reinterpret_cast<__half*>(smem + SB_OFF);
    float4* sA4   = reinterpret_cast<float4*>(smem + SA_OFF);
    float*  sKern = reinterpret_cast<float*>(smem + SKERN_OFF);
    float*  sBias = reinterpret_cast<float*>(smem + SBIAS_OFF);

    const int tid = threadIdx.x;

    // kern[n] = (|si_keys[k]|+1e-10) * sigmoid(si_agents[k][a]); bias[n] = si_b
    if (tid < NN) {
        int k = tid >> 4;
        float sg = 1.0f / (1.0f + __expf(-si_agents[tid]));
        sKern[tid] = (fabsf(si_keys[k]) + 1e-10f) * sg;
        sBias[tid] = si_b[tid];
    }

    // scalar tail outputs (one thread of one CTA)
    if (blockIdx.x == 0 && tid == NTHREADS - 1 && out_size >= Btot + 5) {
        float ssq = 0.f;
        for (int h = 0; h < 4; ++h) {
            float d = 0.f;
            for (int e = 0; e < 64; ++e) d = fmaf(sel[h * 64 + e], keysp[h * 64 + e], d);
            ssq += d * d;
        }
        out[Btot] = 0.001f * ssq;                  // attend_mag_regs
        float aw = 0.0625f;                         // softmax of equal logits
        float ent = -16.0f * (logf(aw + 1e-8f) * aw);
        for (int h = 0; h < 4; ++h) out[Btot + 1 + h] = ent;  // head_entropies
    }

    // Stage B from si_W (fp32, L2-hot): K-permutation fused into packing.
    // dest seg(2blk) = xy-halves of 4 float4s, seg(2blk+1) = zw-halves.
    // Swizzle: seg' = seg ^ (r & 7); 16B segments.
    for (int s = tid; s < 64 * 16; s += NTHREADS) {
        int r = s >> 4, blk = s & 15;
        const float4* src = reinterpret_cast<const float4*>(si_W + r * ND + blk * 16);
        float4 f0 = src[0], f1 = src[1], f2 = src[2], f3 = src[3];
        uint4 seg0, seg1;
        seg0.x = pack_h2(f0.x, f0.y); seg0.y = pack_h2(f1.x, f1.y);
        seg0.z = pack_h2(f2.x, f2.y); seg0.w = pack_h2(f3.x, f3.y);
        seg1.x = pack_h2(f0.z, f0.w); seg1.y = pack_h2(f1.z, f1.w);
        seg1.z = pack_h2(f2.z, f2.w); seg1.w = pack_h2(f3.z, f3.w);
        int c0 = 2 * blk, c1 = 2 * blk + 1;
        *reinterpret_cast<uint4*>(sB + r * ND + ((c0 ^ (r & 7)) << 3)) = seg0;
        *reinterpret_cast<uint4*>(sB + r * ND + ((c1 ^ (r & 7)) << 3)) = seg1;
    }
    __syncthreads();

    const int w = tid >> 5, l = tid & 31;
    const int quad = l >> 2, qid = l & 3;
    const int l7 = l & 7, t8 = l >> 3;
    const long warpRow0 = (long)blockIdx.x * MT + w * 16;

    long r0 = warpRow0 + quad;
    long r1 = r0 + 8;
    long r0c = (r0 < Btot) ? r0 : (long)(Btot - 1);
    long r1c = (r1 < Btot) ? r1 : (long)(Btot - 1);
    const int cA = qid * 2;

    // cp.async lane geometry: lane l owns ring segments l and l+32 (private)
    const int ldRowA = l >> 2;
    const int ldC4A  = l & 3;
    long gRow0 = warpRow0 + ldRowA;       if (gRow0 >= Btot) gRow0 = Btot - 1;
    long gRow1 = warpRow0 + 8 + ldRowA;   if (gRow1 >= Btot) gRow1 = Btot - 1;
    const float* gA0 = acts + gRow0 * ND + ldC4A * 4;
    const float* gA1 = acts + gRow1 * ND + ldC4A * 4;

    const unsigned sAaddr = (unsigned)__cvta_generic_to_shared(sA4);
    const unsigned sBaddr = (unsigned)__cvta_generic_to_shared(sB);
    const unsigned segOff0 = (unsigned)((ldRowA * 4 + ldC4A) * 16);
    const unsigned segOff1 = segOff0 + 8 * 4 * 16;

    // B ldmatrix lane geometry
    const int rowB_off = (t8 >> 1) * 8 + l7;
    const int s0B = t8 & 1;

    float acc[8][4];
#pragma unroll
    for (int i = 0; i < 8; ++i)
#pragma unroll
        for (int j = 0; j < 4; ++j) acc[i][j] = 0.f;

    // prologue: stages for kk = 0..PIPE_D-1
#pragma unroll
    for (int kk = 0; kk < PIPE_D; ++kk) {
        unsigned stBase = sAaddr + (unsigned)((w * NSTAGES + kk) * 1024);
        CP_ASYNC_CG16(stBase + segOff0, gA0 + kk * 16);
        CP_ASYNC_CG16(stBase + segOff1, gA1 + kk * 16);
        CP_COMMIT();
    }

    // hoisted adv_q inputs: complete under the mainloop's shadow
    const float v = Vp[0] * 0.0625f;
    const float* aqr0 = aq + r0c * NA;
    const float* aqr1 = aq + r1c * NA;
    const float* mqr0 = mq + r0c * NA;
    const float* mqr1 = mq + r1c * NA;
    float2 aq0a = __ldcs((const float2*)(aqr0 + cA));
    float2 aq0b = __ldcs((const float2*)(aqr0 + cA + 8));
    float2 aq1a = __ldcs((const float2*)(aqr1 + cA));
    float2 aq1b = __ldcs((const float2*)(aqr1 + cA + 8));
    float2 mq0a = __ldcs((const float2*)(mqr0 + cA));
    float2 mq0b = __ldcs((const float2*)(mqr0 + cA + 8));
    float2 mq1a = __ldcs((const float2*)(mqr1 + cA));
    float2 mq1b = __ldcs((const float2*)(mqr1 + cA + 8));
    // advq[h][pp*2+j]: row h in {r0,r1}, a = cA + j + 8*pp
    float advq[2][4];
    advq[0][0] = fmaf(0.25f, aq0a.x, v) - fmaf(0.25f, mq0a.x, v);
    advq[0][1] = fmaf(0.25f, aq0a.y, v) - fmaf(0.25f, mq0a.y, v);
    advq[0][2] = fmaf(0.25f, aq0b.x, v) - fmaf(0.25f, mq0b.x, v);
    advq[0][3] = fmaf(0.25f, aq0b.y, v) - fmaf(0.25f, mq0b.y, v);
    advq[1][0] = fmaf(0.25f, aq1a.x, v) - fmaf(0.25f, mq1a.x, v);
    advq[1][1] = fmaf(0.25f, aq1a.y, v) - fmaf(0.25f, mq1a.y, v);
    advq[1][2] = fmaf(0.25f, aq1b.x, v) - fmaf(0.25f, mq1b.x, v);
    advq[1][3] = fmaf(0.25f, aq1b.y, v) - fmaf(0.25f, mq1b.y, v);

#pragma unroll
    for (int kk = 0; kk < 16; ++kk) {
        if (kk + PIPE_D < 16) {
            unsigned stBase = sAaddr + (unsigned)((w * NSTAGES + ((kk + PIPE_D) % NSTAGES)) * 1024);
            CP_ASYNC_CG16(stBase + segOff0, gA0 + (kk + PIPE_D) * 16);
            CP_ASYNC_CG16(stBase + segOff1, gA1 + (kk + PIPE_D) * 16);
        }
        CP_COMMIT();
        CP_WAIT();            // stage kk complete (lane-private data -> no sync)

        const float4* st = sA4 + (w * NSTAGES + (kk % NSTAGES)) * 64;
        float4 f0 = st[quad * 4 + qid];        // = float4 #l  (own segment)
        float4 f1 = st[(quad + 8) * 4 + qid];  // = float4 #(l+32) (own segment)
        unsigned a0 = pack_h2(f0.x, f0.y);
        unsigned a1 = pack_h2(f1.x, f1.y);
        unsigned a2 = pack_h2(f0.z, f0.w);
        unsigned a3 = pack_h2(f1.z, f1.w);
#pragma unroll
        for (int p = 0; p < 4; ++p) {
            unsigned addrB = sBaddr
                           + (unsigned)((p * 16 + rowB_off) * (ND * 2))
                           + (unsigned)(((kk * 2 + s0B) ^ l7) << 4);
            unsigned b0, b1, b2, b3;
            asm volatile("ldmatrix.sync.aligned.m8n8.x4.shared.b16 {%0,%1,%2,%3}, [%4];\n"
                         : "=r"(b0), "=r"(b1), "=r"(b2), "=r"(b3) : "r"(addrB));
            asm volatile("mma.sync.aligned.m16n8k16.row.col.f32.f16.f16.f32 "
                         "{%0,%1,%2,%3}, {%4,%5,%6,%7}, {%8,%9}, {%0,%1,%2,%3};\n"
                         : "+f"(acc[2*p][0]), "+f"(acc[2*p][1]),
                           "+f"(acc[2*p][2]), "+f"(acc[2*p][3])
                         : "r"(a0), "r"(a1), "r"(a2), "r"(a3), "r"(b0), "r"(b1));
            asm volatile("mma.sync.aligned.m16n8k16.row.col.f32.f16.f16.f32 "
                         "{%0,%1,%2,%3}, {%4,%5,%6,%7}, {%8,%9}, {%0,%1,%2,%3};\n"
                         : "+f"(acc[2*p+1][0]), "+f"(acc[2*p+1][1]),
                           "+f"(acc[2*p+1][2]), "+f"(acc[2*p+1][3])
                         : "r"(a0), "r"(a1), "r"(a2), "r"(a3), "r"(b2), "r"(b3));
        }
    }

    // Epilogue. acc[nt][h*2+j] = logit for row (r0 + h*8), col n = nt*8 + cA + j.
    float partial[2] = {0.f, 0.f};
#pragma unroll
    for (int h = 0; h < 2; ++h) {
#pragma unroll
        for (int j = 0; j < 2; ++j) {
#pragma unroll
            for (int pp = 0; pp < 2; ++pp) {
                float s = 0.f;
#pragma unroll
                for (int q = 0; q < 4; ++q) {
                    int nt = 2 * q + pp;
                    int n = nt * 8 + cA + j;
                    float x = acc[nt][h * 2 + j] + sBias[n];
                    x = 1.0f / (1.0f + __expf(-x));
                    s = fmaf(x, sKern[n], s);
                }
                partial[h] += advq[h][pp * 2 + j] * (s - 1.0f);
            }
        }
    }
    partial[0] += __shfl_xor_sync(0xffffffffu, partial[0], 1);
    partial[0] += __shfl_xor_sync(0xffffffffu, partial[0], 2);
    partial[1] += __shfl_xor_sync(0xffffffffu, partial[1], 1);
    partial[1] += __shfl_xor_sync(0xffffffffu, partial[1], 2);
    if (qid == 0) {
        if (r0 < Btot) out[r0] = partial[0];
        if (r1 < Btot) out[r1] = partial[1];
    }
}

// ---------------------------------------------------------------------------
extern "C" void kernel_launch(void* const* d_in, const int* in_sizes, int n_in,
                              void* d_out, int out_size)
{
    const float* agent_qs  = (const float*)d_in[0];
    const float* actions   = (const float*)d_in[1];
    const float* max_q_i   = (const float*)d_in[2];
    const float* selectors = (const float*)d_in[3];
    const float* keys      = (const float*)d_in[4];
    const float* V         = (const float*)d_in[5];
    const float* si_keys   = (const float*)d_in[6];
    const float* si_agents = (const float*)d_in[7];
    const float* si_W      = (const float*)d_in[8];
    const float* si_b      = (const float*)d_in[9];
    float* out = (float*)d_out;

    int Btot = in_sizes[0] / NA;   // B0*T

    cudaFuncSetAttribute(mixer_kernel,
                         cudaFuncAttributeMaxDynamicSharedMemorySize, SMEM_TOTAL);

    int grid = (Btot + MT - 1) / MT;
    mixer_kernel<<<grid, NTHREADS, SMEM_TOTAL>>>(agent_qs, actions, max_q_i, V,
                                                 selectors, keys,
                                                 si_keys, si_agents, si_W, si_b,
                                                 out, Btot, out_size);
}

// round 9
// speedup vs baseline: 1.1931x; 1.1547x over previous
#include <cuda_runtime.h>
#include <cuda_fp16.h>

#define NA 16       // agents
#define ND 256      // action dim (K of the GEMM)
#define NN 64       // K_kernels * NA = output cols (N of the GEMM)
#define MT 128      // rows per tile (8 warps x 16)
#define NTHREADS 256
#define NWARPS 8
#define NSTAGES 5   // per-warp cp.async A stages (1KB each)
#define PIPE_D 3    // wait_group depth
#define GRID 444    // 148 SMs x 3 CTAs: persistent

// dynamic smem layout (bytes)
#define SB_OFF    0                        // B tile fp16: 32KB
#define SA_OFF    32768                    // A ring: 8 warps * 5 stages * 1KB = 40KB
#define SKERN_OFF (32768 + NWARPS*NSTAGES*1024)
#define SBIAS_OFF (SKERN_OFF + 256)
#define SMEM_TOTAL (SBIAS_OFF + 256)       // 74240 -> 3 CTAs/SM

__device__ __forceinline__ unsigned pack_h2(float a, float b) {
    __half2 h = __floats2half2_rn(a, b);
    return *reinterpret_cast<unsigned*>(&h);
}

#define CP_ASYNC_CG16(dst_u32, src_ptr) \
    asm volatile("cp.async.cg.shared.global [%0], [%1], 16;\n" :: "r"(dst_u32), "l"(src_ptr))
#define CP_COMMIT()  asm volatile("cp.async.commit_group;\n" ::: "memory")
#define CP_WAIT()    asm volatile("cp.async.wait_group %0;\n" :: "n"(PIPE_D) : "memory")

// ---------------------------------------------------------------------------
// Persistent fused kernel: B staged ONCE per CTA (K-permuted fp32->fp16,
// swizzled), then grid-stride over row tiles. Per tile: per-warp lane-private
// cp.async A ring + fp16 mma.sync + fused sigmoid/kern/adv epilogue.
// ---------------------------------------------------------------------------
__global__ void __launch_bounds__(NTHREADS, 3)
mixer_kernel(const float* __restrict__ aq,
             const float* __restrict__ acts,
             const float* __restrict__ mq,
             const float* __restrict__ Vp,
             const float* __restrict__ sel,
             const float* __restrict__ keysp,
             const float* __restrict__ si_keys,
             const float* __restrict__ si_agents,
             const float* __restrict__ si_W,
             const float* __restrict__ si_b,
             float* __restrict__ out,
             int Btot, int out_size)
{
    extern __shared__ char smem[];
    __half* sB    = reinterpret_cast<__half*>(smem + SB_OFF);
    float4* sA4   = reinterpret_cast<float4*>(smem + SA_OFF);
    float*  sKern = reinterpret_cast<float*>(smem + SKERN_OFF);
    float*  sBias = reinterpret_cast<float*>(smem + SBIAS_OFF);

    const int tid = threadIdx.x;

    // kern[n] = (|si_keys[k]|+1e-10) * sigmoid(si_agents[k][a]); bias[n] = si_b
    if (tid < NN) {
        int k = tid >> 4;
        float sg = 1.0f / (1.0f + __expf(-si_agents[tid]));
        sKern[tid] = (fabsf(si_keys[k]) + 1e-10f) * sg;
        sBias[tid] = si_b[tid];
    }

    // scalar tail outputs (one thread of one CTA)
    if (blockIdx.x == 0 && tid == NTHREADS - 1 && out_size >= Btot + 5) {
        float ssq = 0.f;
        for (int h = 0; h < 4; ++h) {
            float d = 0.f;
            for (int e = 0; e < 64; ++e) d = fmaf(sel[h * 64 + e], keysp[h * 64 + e], d);
            ssq += d * d;
        }
        out[Btot] = 0.001f * ssq;                  // attend_mag_regs
        float aw = 0.0625f;                         // softmax of equal logits
        float ent = -16.0f * (logf(aw + 1e-8f) * aw);
        for (int h = 0; h < 4; ++h) out[Btot + 1 + h] = ent;  // head_entropies
    }

    // Stage B ONCE from si_W (fp32, L2-hot): K-permutation fused into packing.
    // dest seg(2blk) = xy-halves of 4 float4s, seg(2blk+1) = zw-halves.
    // Swizzle: seg' = seg ^ (r & 7); 16B segments.
    for (int s = tid; s < 64 * 16; s += NTHREADS) {
        int r = s >> 4, blk = s & 15;
        const float4* src = reinterpret_cast<const float4*>(si_W + r * ND + blk * 16);
        float4 f0 = src[0], f1 = src[1], f2 = src[2], f3 = src[3];
        uint4 seg0, seg1;
        seg0.x = pack_h2(f0.x, f0.y); seg0.y = pack_h2(f1.x, f1.y);
        seg0.z = pack_h2(f2.x, f2.y); seg0.w = pack_h2(f3.x, f3.y);
        seg1.x = pack_h2(f0.z, f0.w); seg1.y = pack_h2(f1.z, f1.w);
        seg1.z = pack_h2(f2.z, f2.w); seg1.w = pack_h2(f3.z, f3.w);
        int c0 = 2 * blk, c1 = 2 * blk + 1;
        *reinterpret_cast<uint4*>(sB + r * ND + ((c0 ^ (r & 7)) << 3)) = seg0;
        *reinterpret_cast<uint4*>(sB + r * ND + ((c1 ^ (r & 7)) << 3)) = seg1;
    }
    __syncthreads();

    // warp-constant geometry
    const int w = tid >> 5, l = tid & 31;
    const int quad = l >> 2, qid = l & 3;
    const int l7 = l & 7, t8 = l >> 3;
    const int cA = qid * 2;
    const int ldRowA = l >> 2;            // cp.async: lane l owns segs l, l+32
    const int ldC4A  = l & 3;

    const unsigned sAaddr = (unsigned)__cvta_generic_to_shared(sA4);
    const unsigned sBaddr = (unsigned)__cvta_generic_to_shared(sB);
    const unsigned segOff0 = (unsigned)((ldRowA * 4 + ldC4A) * 16);
    const unsigned segOff1 = segOff0 + 8 * 4 * 16;
    const int rowB_off = (t8 >> 1) * 8 + l7;   // ldmatrix lane geometry
    const int s0B = t8 & 1;

    const float v = Vp[0] * 0.0625f;
    const int ntiles = (Btot + MT - 1) / MT;

    for (int tile = blockIdx.x; tile < ntiles; tile += GRID) {
        const long warpRow0 = (long)tile * MT + w * 16;

        long r0 = warpRow0 + quad;
        long r1 = r0 + 8;
        long r0c = (r0 < Btot) ? r0 : (long)(Btot - 1);
        long r1c = (r1 < Btot) ? r1 : (long)(Btot - 1);

        long gRow0 = warpRow0 + ldRowA;       if (gRow0 >= Btot) gRow0 = Btot - 1;
        long gRow1 = warpRow0 + 8 + ldRowA;   if (gRow1 >= Btot) gRow1 = Btot - 1;
        const float* gA0 = acts + gRow0 * ND + ldC4A * 4;
        const float* gA1 = acts + gRow1 * ND + ldC4A * 4;

        __syncwarp();   // guard ring WAR across tile boundary

        // prologue: stages for kk = 0..PIPE_D-1
#pragma unroll
        for (int kk = 0; kk < PIPE_D; ++kk) {
            unsigned stBase = sAaddr + (unsigned)((w * NSTAGES + kk) * 1024);
            CP_ASYNC_CG16(stBase + segOff0, gA0 + kk * 16);
            CP_ASYNC_CG16(stBase + segOff1, gA1 + kk * 16);
            CP_COMMIT();
        }

        // hoisted adv_q inputs: complete under the mainloop's shadow
        const float* aqr0 = aq + r0c * NA;
        const float* aqr1 = aq + r1c * NA;
        const float* mqr0 = mq + r0c * NA;
        const float* mqr1 = mq + r1c * NA;
        float2 aq0a = __ldcs((const float2*)(aqr0 + cA));
        float2 aq0b = __ldcs((const float2*)(aqr0 + cA + 8));
        float2 aq1a = __ldcs((const float2*)(aqr1 + cA));
        float2 aq1b = __ldcs((const float2*)(aqr1 + cA + 8));
        float2 mq0a = __ldcs((const float2*)(mqr0 + cA));
        float2 mq0b = __ldcs((const float2*)(mqr0 + cA + 8));
        float2 mq1a = __ldcs((const float2*)(mqr1 + cA));
        float2 mq1b = __ldcs((const float2*)(mqr1 + cA + 8));
        float advq[2][4];
        advq[0][0] = fmaf(0.25f, aq0a.x, v) - fmaf(0.25f, mq0a.x, v);
        advq[0][1] = fmaf(0.25f, aq0a.y, v) - fmaf(0.25f, mq0a.y, v);
        advq[0][2] = fmaf(0.25f, aq0b.x, v) - fmaf(0.25f, mq0b.x, v);
        advq[0][3] = fmaf(0.25f, aq0b.y, v) - fmaf(0.25f, mq0b.y, v);
        advq[1][0] = fmaf(0.25f, aq1a.x, v) - fmaf(0.25f, mq1a.x, v);
        advq[1][1] = fmaf(0.25f, aq1a.y, v) - fmaf(0.25f, mq1a.y, v);
        advq[1][2] = fmaf(0.25f, aq1b.x, v) - fmaf(0.25f, mq1b.x, v);
        advq[1][3] = fmaf(0.25f, aq1b.y, v) - fmaf(0.25f, mq1b.y, v);

        float acc[8][4];
#pragma unroll
        for (int i = 0; i < 8; ++i)
#pragma unroll
            for (int j = 0; j < 4; ++j) acc[i][j] = 0.f;

#pragma unroll
        for (int kk = 0; kk < 16; ++kk) {
            if (kk + PIPE_D < 16) {
                unsigned stBase = sAaddr + (unsigned)((w * NSTAGES + ((kk + PIPE_D) % NSTAGES)) * 1024);
                CP_ASYNC_CG16(stBase + segOff0, gA0 + (kk + PIPE_D) * 16);
                CP_ASYNC_CG16(stBase + segOff1, gA1 + (kk + PIPE_D) * 16);
            }
            CP_COMMIT();
            CP_WAIT();        // stage kk complete (lane-private -> no warp sync)

            const float4* st = sA4 + (w * NSTAGES + (kk % NSTAGES)) * 64;
            float4 f0 = st[quad * 4 + qid];
            float4 f1 = st[(quad + 8) * 4 + qid];
            unsigned a0 = pack_h2(f0.x, f0.y);
            unsigned a1 = pack_h2(f1.x, f1.y);
            unsigned a2 = pack_h2(f0.z, f0.w);
            unsigned a3 = pack_h2(f1.z, f1.w);
#pragma unroll
            for (int p = 0; p < 4; ++p) {
                unsigned addrB = sBaddr
                               + (unsigned)((p * 16 + rowB_off) * (ND * 2))
                               + (unsigned)(((kk * 2 + s0B) ^ l7) << 4);
                unsigned b0, b1, b2, b3;
                asm volatile("ldmatrix.sync.aligned.m8n8.x4.shared.b16 {%0,%1,%2,%3}, [%4];\n"
                             : "=r"(b0), "=r"(b1), "=r"(b2), "=r"(b3) : "r"(addrB));
                asm volatile("mma.sync.aligned.m16n8k16.row.col.f32.f16.f16.f32 "
                             "{%0,%1,%2,%3}, {%4,%5,%6,%7}, {%8,%9}, {%0,%1,%2,%3};\n"
                             : "+f"(acc[2*p][0]), "+f"(acc[2*p][1]),
                               "+f"(acc[2*p][2]), "+f"(acc[2*p][3])
                             : "r"(a0), "r"(a1), "r"(a2), "r"(a3), "r"(b0), "r"(b1));
                asm volatile("mma.sync.aligned.m16n8k16.row.col.f32.f16.f16.f32 "
                             "{%0,%1,%2,%3}, {%4,%5,%6,%7}, {%8,%9}, {%0,%1,%2,%3};\n"
                             : "+f"(acc[2*p+1][0]), "+f"(acc[2*p+1][1]),
                               "+f"(acc[2*p+1][2]), "+f"(acc[2*p+1][3])
                             : "r"(a0), "r"(a1), "r"(a2), "r"(a3), "r"(b2), "r"(b3));
            }
        }

        // Epilogue. acc[nt][h*2+j] = row (r0 + h*8), col n = nt*8 + cA + j.
        float partial[2] = {0.f, 0.f};
#pragma unroll
        for (int h = 0; h < 2; ++h) {
#pragma unroll
            for (int j = 0; j < 2; ++j) {
#pragma unroll
                for (int pp = 0; pp < 2; ++pp) {
                    float s = 0.f;
#pragma unroll
                    for (int q = 0; q < 4; ++q) {
                        int nt = 2 * q + pp;
                        int n = nt * 8 + cA + j;
                        float x = acc[nt][h * 2 + j] + sBias[n];
                        x = 1.0f / (1.0f + __expf(-x));
                        s = fmaf(x, sKern[n], s);
                    }
                    partial[h] += advq[h][pp * 2 + j] * (s - 1.0f);
                }
            }
        }
        partial[0] += __shfl_xor_sync(0xffffffffu, partial[0], 1);
        partial[0] += __shfl_xor_sync(0xffffffffu, partial[0], 2);
        partial[1] += __shfl_xor_sync(0xffffffffu, partial[1], 1);
        partial[1] += __shfl_xor_sync(0xffffffffu, partial[1], 2);
        if (qid == 0) {
            if (r0 < Btot) out[r0] = partial[0];
            if (r1 < Btot) out[r1] = partial[1];
        }
    }
}

// ---------------------------------------------------------------------------
extern "C" void kernel_launch(void* const* d_in, const int* in_sizes, int n_in,
                              void* d_out, int out_size)
{
    const float* agent_qs  = (const float*)d_in[0];
    const float* actions   = (const float*)d_in[1];
    const float* max_q_i   = (const float*)d_in[2];
    const float* selectors = (const float*)d_in[3];
    const float* keys      = (const float*)d_in[4];
    const float* V         = (const float*)d_in[5];
    const float* si_keys   = (const float*)d_in[6];
    const float* si_agents = (const float*)d_in[7];
    const float* si_W      = (const float*)d_in[8];
    const float* si_b      = (const float*)d_in[9];
    float* out = (float*)d_out;

    int Btot = in_sizes[0] / NA;   // B0*T

    cudaFuncSetAttribute(mixer_kernel,
                         cudaFuncAttributeMaxDynamicSharedMemorySize, SMEM_TOTAL);

    int ntiles = (Btot + MT - 1) / MT;
    int grid = ntiles < GRID ? ntiles : GRID;
    mixer_kernel<<<grid, NTHREADS, SMEM_TOTAL>>>(agent_qs, actions, max_q_i, V,
                                                 selectors, keys,
                                                 si_keys, si_agents, si_W, si_b,
                                                 out, Btot, out_size);
}

// round 13
// speedup vs baseline: 1.2515x; 1.0489x over previous
#include <cuda_runtime.h>
#include <cuda_fp16.h>

#define NA 16       // agents
#define ND 256      // action dim (K of the GEMM)
#define NN 64       // K_kernels * NA = output cols (N of the GEMM)
#define MT 128      // rows per tile (8 warps x 16)
#define NTHREADS 256
#define NWARPS 8
#define NSTAGES 5   // per-warp cp.async A stages (1KB each)
#define PIPE_D 4    // wait_group depth (safe with 5 stages: WAR dist analysis)
#define GRID 444    // 148 SMs x 3 CTAs: persistent

// dynamic smem layout (bytes)
#define SB_OFF    0                        // B tile fp16: 32KB
#define SA_OFF    32768                    // A ring: 8 warps * 5 stages * 1KB = 40KB
#define SKERN_OFF (32768 + NWARPS*NSTAGES*1024)
#define SBIAS_OFF (SKERN_OFF + 256)
#define SMEM_TOTAL (SBIAS_OFF + 256)       // 74240 -> 3 CTAs/SM

__device__ __forceinline__ unsigned pack_h2(float a, float b) {
    __half2 h = __floats2half2_rn(a, b);
    return *reinterpret_cast<unsigned*>(&h);
}

#define CP_ASYNC_CG16(dst_u32, src_ptr) \
    asm volatile("cp.async.cg.shared.global [%0], [%1], 16;\n" :: "r"(dst_u32), "l"(src_ptr))
#define CP_COMMIT()  asm volatile("cp.async.commit_group;\n" ::: "memory")
#define CP_WAIT()    asm volatile("cp.async.wait_group %0;\n" :: "n"(PIPE_D) : "memory")

// ---------------------------------------------------------------------------
// Persistent fused kernel, cross-tile flattened cp.async pipeline:
// ring slot = (global iter) mod NSTAGES; the tail iterations of tile t
// prefetch the head k-steps of tile t+GRID, so the pipe never drains.
// ---------------------------------------------------------------------------
__global__ void __launch_bounds__(NTHREADS, 3)
mixer_kernel(const float* __restrict__ aq,
             const float* __restrict__ acts,
             const float* __restrict__ mq,
             const float* __restrict__ Vp,
             const float* __restrict__ sel,
             const float* __restrict__ keysp,
             const float* __restrict__ si_keys,
             const float* __restrict__ si_agents,
             const float* __restrict__ si_W,
             const float* __restrict__ si_b,
             float* __restrict__ out,
             int Btot, int out_size)
{
    extern __shared__ char smem[];
    __half* sB    = reinterpret_cast<__half*>(smem + SB_OFF);
    float4* sA4   = reinterpret_cast<float4*>(smem + SA_OFF);
    float*  sKern = reinterpret_cast<float*>(smem + SKERN_OFF);
    float*  sBias = reinterpret_cast<float*>(smem + SBIAS_OFF);

    const int tid = threadIdx.x;

    // kern[n] = (|si_keys[k]|+1e-10) * sigmoid(si_agents[k][a]); bias[n] = si_b
    if (tid < NN) {
        int k = tid >> 4;
        float sg = 1.0f / (1.0f + __expf(-si_agents[tid]));
        sKern[tid] = (fabsf(si_keys[k]) + 1e-10f) * sg;
        sBias[tid] = si_b[tid];
    }

    // scalar tail outputs (one thread of one CTA)
    if (blockIdx.x == 0 && tid == NTHREADS - 1 && out_size >= Btot + 5) {
        float ssq = 0.f;
        for (int h = 0; h < 4; ++h) {
            float d = 0.f;
            for (int e = 0; e < 64; ++e) d = fmaf(sel[h * 64 + e], keysp[h * 64 + e], d);
            ssq += d * d;
        }
        out[Btot] = 0.001f * ssq;                  // attend_mag_regs
        float aw = 0.0625f;                         // softmax of equal logits
        float ent = -16.0f * (logf(aw + 1e-8f) * aw);
        for (int h = 0; h < 4; ++h) out[Btot + 1 + h] = ent;  // head_entropies
    }

    // Stage B ONCE from si_W: K-permutation fused into packing.
    // dest seg(2blk) = xy-halves of 4 float4s, seg(2blk+1) = zw-halves.
    // Swizzle: seg' = seg ^ (r & 7); 16B segments.
    for (int s = tid; s < 64 * 16; s += NTHREADS) {
        int r = s >> 4, blk = s & 15;
        const float4* src = reinterpret_cast<const float4*>(si_W + r * ND + blk * 16);
        float4 f0 = src[0], f1 = src[1], f2 = src[2], f3 = src[3];
        uint4 seg0, seg1;
        seg0.x = pack_h2(f0.x, f0.y); seg0.y = pack_h2(f1.x, f1.y);
        seg0.z = pack_h2(f2.x, f2.y); seg0.w = pack_h2(f3.x, f3.y);
        seg1.x = pack_h2(f0.z, f0.w); seg1.y = pack_h2(f1.z, f1.w);
        seg1.z = pack_h2(f2.z, f2.w); seg1.w = pack_h2(f3.z, f3.w);
        int c0 = 2 * blk, c1 = 2 * blk + 1;
        *reinterpret_cast<uint4*>(sB + r * ND + ((c0 ^ (r & 7)) << 3)) = seg0;
        *reinterpret_cast<uint4*>(sB + r * ND + ((c1 ^ (r & 7)) << 3)) = seg1;
    }
    __syncthreads();

    // warp-constant geometry
    const int w = tid >> 5, l = tid & 31;
    const int quad = l >> 2, qid = l & 3;
    const int l7 = l & 7, t8 = l >> 3;
    const int cA = qid * 2;
    const int ldRowA = l >> 2;            // cp.async: lane l owns segs l, l+32
    const int ldC4A  = l & 3;

    const unsigned sAaddr = (unsigned)__cvta_generic_to_shared(sA4) + (unsigned)(w * NSTAGES * 1024);
    const unsigned sBaddr = (unsigned)__cvta_generic_to_shared(sB);
    const unsigned segOff0 = (unsigned)((ldRowA * 4 + ldC4A) * 16);
    const unsigned segOff1 = segOff0 + 8 * 4 * 16;
    const int rowB_off = (t8 >> 1) * 8 + l7;   // ldmatrix lane geometry
    const int s0B = t8 & 1;

    const float v = Vp[0] * 0.0625f;
    const int ntiles = (Btot + MT - 1) / MT;

    int tile = blockIdx.x;
    if (tile >= ntiles) return;

    // per-tile A pointer computation (clamped)
    const float *gA0, *gA1;
    {
        long wr0 = (long)tile * MT + w * 16;
        long g0 = wr0 + ldRowA;      if (g0 >= Btot) g0 = Btot - 1;
        long g1 = wr0 + 8 + ldRowA;  if (g1 >= Btot) g1 = Btot - 1;
        gA0 = acts + g0 * ND + ldC4A * 4;
        gA1 = acts + g1 * ND + ldC4A * 4;
    }

    int ringOff = 0;   // ring slot offset for current tile (global-iter mod 5)

    // prologue: first PIPE_D k-steps of the first tile (slots 0..3)
#pragma unroll
    for (int kk = 0; kk < PIPE_D; ++kk) {
        unsigned stBase = sAaddr + (unsigned)(kk * 1024);
        CP_ASYNC_CG16(stBase + segOff0, gA0 + kk * 16);
        CP_ASYNC_CG16(stBase + segOff1, gA1 + kk * 16);
        CP_COMMIT();
    }

    while (true) {
        const int nextTile = tile + GRID;
        const bool hasNext = nextTile < ntiles;
        const float *nA0 = gA0, *nA1 = gA1;
        if (hasNext) {
            long wr0 = (long)nextTile * MT + w * 16;
            long g0 = wr0 + ldRowA;      if (g0 >= Btot) g0 = Btot - 1;
            long g1 = wr0 + 8 + ldRowA;  if (g1 >= Btot) g1 = Btot - 1;
            nA0 = acts + g0 * ND + ldC4A * 4;
            nA1 = acts + g1 * ND + ldC4A * 4;
        }

        const long warpRow0 = (long)tile * MT + w * 16;
        long r0 = warpRow0 + quad;
        long r1 = r0 + 8;
        long r0c = (r0 < Btot) ? r0 : (long)(Btot - 1);
        long r1c = (r1 < Btot) ? r1 : (long)(Btot - 1);

        // hoisted adv_q inputs: complete under the mainloop's shadow
        const float* aqr0 = aq + r0c * NA;
        const float* aqr1 = aq + r1c * NA;
        const float* mqr0 = mq + r0c * NA;
        const float* mqr1 = mq + r1c * NA;
        float2 aq0a = __ldcs((const float2*)(aqr0 + cA));
        float2 aq0b = __ldcs((const float2*)(aqr0 + cA + 8));
        float2 aq1a = __ldcs((const float2*)(aqr1 + cA));
        float2 aq1b = __ldcs((const float2*)(aqr1 + cA + 8));
        float2 mq0a = __ldcs((const float2*)(mqr0 + cA));
        float2 mq0b = __ldcs((const float2*)(mqr0 + cA + 8));
        float2 mq1a = __ldcs((const float2*)(mqr1 + cA));
        float2 mq1b = __ldcs((const float2*)(mqr1 + cA + 8));
        float advq[2][4];
        advq[0][0] = fmaf(0.25f, aq0a.x, v) - fmaf(0.25f, mq0a.x, v);
        advq[0][1] = fmaf(0.25f, aq0a.y, v) - fmaf(0.25f, mq0a.y, v);
        advq[0][2] = fmaf(0.25f, aq0b.x, v) - fmaf(0.25f, mq0b.x, v);
        advq[0][3] = fmaf(0.25f, aq0b.y, v) - fmaf(0.25f, mq0b.y, v);
        advq[1][0] = fmaf(0.25f, aq1a.x, v) - fmaf(0.25f, mq1a.x, v);
        advq[1][1] = fmaf(0.25f, aq1a.y, v) - fmaf(0.25f, mq1a.y, v);
        advq[1][2] = fmaf(0.25f, aq1b.x, v) - fmaf(0.25f, mq1b.x, v);
        advq[1][3] = fmaf(0.25f, aq1b.y, v) - fmaf(0.25f, mq1b.y, v);

        float acc[8][4];
#pragma unroll
        for (int i = 0; i < 8; ++i)
#pragma unroll
            for (int j = 0; j < 4; ++j) acc[i][j] = 0.f;

#pragma unroll
        for (int kk = 0; kk < 16; ++kk) {
            // prefetch global-iteration (this + PIPE_D): same tile or next tile
            {
                int pre = kk + PIPE_D;
                int slot = (ringOff + pre) % NSTAGES;   // FULL mod
                unsigned stBase = sAaddr + (unsigned)(slot * 1024);
                if (pre < 16) {
                    CP_ASYNC_CG16(stBase + segOff0, gA0 + pre * 16);
                    CP_ASYNC_CG16(stBase + segOff1, gA1 + pre * 16);
                } else {
                    int pk = pre - 16;              // next tile k-steps 0..PIPE_D-1
                    CP_ASYNC_CG16(stBase + segOff0, nA0 + pk * 16);
                    CP_ASYNC_CG16(stBase + segOff1, nA1 + pk * 16);
                }
            }
            CP_COMMIT();
            CP_WAIT();        // groups <= PIPE_D outstanding -> iter kk complete

            int cslot = (ringOff + kk) % NSTAGES;       // FULL mod
            const float4* st = sA4 + (w * NSTAGES + cslot) * 64;
            float4 f0 = st[quad * 4 + qid];
            float4 f1 = st[(quad + 8) * 4 + qid];
            unsigned a0 = pack_h2(f0.x, f0.y);
            unsigned a1 = pack_h2(f1.x, f1.y);
            unsigned a2 = pack_h2(f0.z, f0.w);
            unsigned a3 = pack_h2(f1.z, f1.w);
#pragma unroll
            for (int p = 0; p < 4; ++p) {
                unsigned addrB = sBaddr
                               + (unsigned)((p * 16 + rowB_off) * (ND * 2))
                               + (unsigned)(((kk * 2 + s0B) ^ l7) << 4);
                unsigned b0, b1, b2, b3;
                asm volatile("ldmatrix.sync.aligned.m8n8.x4.shared.b16 {%0,%1,%2,%3}, [%4];\n"
                             : "=r"(b0), "=r"(b1), "=r"(b2), "=r"(b3) : "r"(addrB));
                asm volatile("mma.sync.aligned.m16n8k16.row.col.f32.f16.f16.f32 "
                             "{%0,%1,%2,%3}, {%4,%5,%6,%7}, {%8,%9}, {%0,%1,%2,%3};\n"
                             : "+f"(acc[2*p][0]), "+f"(acc[2*p][1]),
                               "+f"(acc[2*p][2]), "+f"(acc[2*p][3])
                             : "r"(a0), "r"(a1), "r"(a2), "r"(a3), "r"(b0), "r"(b1));
                asm volatile("mma.sync.aligned.m16n8k16.row.col.f32.f16.f16.f32 "
                             "{%0,%1,%2,%3}, {%4,%5,%6,%7}, {%8,%9}, {%0,%1,%2,%3};\n"
                             : "+f"(acc[2*p+1][0]), "+f"(acc[2*p+1][1]),
                               "+f"(acc[2*p+1][2]), "+f"(acc[2*p+1][3])
                             : "r"(a0), "r"(a1), "r"(a2), "r"(a3), "r"(b2), "r"(b3));
            }
        }

        // Epilogue. acc[nt][h*2+j] = row (r0 + h*8), col n = nt*8 + cA + j.
        float partial[2] = {0.f, 0.f};
#pragma unroll
        for (int h = 0; h < 2; ++h) {
#pragma unroll
            for (int j = 0; j < 2; ++j) {
#pragma unroll
                for (int pp = 0; pp < 2; ++pp) {
                    float s = 0.f;
#pragma unroll
                    for (int q = 0; q < 4; ++q) {
                        int nt = 2 * q + pp;
                        int n = nt * 8 + cA + j;
                        float x = acc[nt][h * 2 + j] + sBias[n];
                        x = 1.0f / (1.0f + __expf(-x));
                        s = fmaf(x, sKern[n], s);
                    }
                    partial[h] += advq[h][pp * 2 + j] * (s - 1.0f);
                }
            }
        }
        partial[0] += __shfl_xor_sync(0xffffffffu, partial[0], 1);
        partial[0] += __shfl_xor_sync(0xffffffffu, partial[0], 2);
        partial[1] += __shfl_xor_sync(0xffffffffu, partial[1], 1);
        partial[1] += __shfl_xor_sync(0xffffffffu, partial[1], 2);
        if (qid == 0) {
            if (r0 < Btot) out[r0] = partial[0];
            if (r1 < Btot) out[r1] = partial[1];
        }

        if (!hasNext) break;
        tile = nextTile;
        gA0 = nA0; gA1 = nA1;
        ringOff += 1;                         // 16 mod 5
        if (ringOff >= NSTAGES) ringOff -= NSTAGES;
    }
}

// ---------------------------------------------------------------------------
extern "C" void kernel_launch(void* const* d_in, const int* in_sizes, int n_in,
                              void* d_out, int out_size)
{
    const float* agent_qs  = (const float*)d_in[0];
    const float* actions   = (const float*)d_in[1];
    const float* max_q_i   = (const float*)d_in[2];
    const float* selectors = (const float*)d_in[3];
    const float* keys      = (const float*)d_in[4];
    const float* V         = (const float*)d_in[5];
    const float* si_keys   = (const float*)d_in[6];
    const float* si_agents = (const float*)d_in[7];
    const float* si_W      = (const float*)d_in[8];
    const float* si_b      = (const float*)d_in[9];
    float* out = (float*)d_out;

    int Btot = in_sizes[0] / NA;   // B0*T

    cudaFuncSetAttribute(mixer_kernel,
                         cudaFuncAttributeMaxDynamicSharedMemorySize, SMEM_TOTAL);

    int ntiles = (Btot + MT - 1) / MT;
    int grid = ntiles < GRID ? ntiles : GRID;
    mixer_kernel<<<grid, NTHREADS, SMEM_TOTAL>>>(agent_qs, actions, max_q_i, V,
                                                 selectors, keys,
                                                 si_keys, si_agents, si_W, si_b,
                                                 out, Btot, out_size);
}